// round 7
// baseline (speedup 1.0000x reference)
#include <cuda_runtime.h>
#include <cuda_bf16.h>

// LearnablePeakExtractor: smooth = x * sig(10*(x-thresh)) * sig(10*(x-pooled5))
//                         mask   = smooth >= thresh
// Fused: sig(a)*sig(b) = 1/((1+e^-a)(1+e^-b)) -> 2 EX2 + 1 RCP per element.
// R6: dual-row tile (2 independent 256-bit load streams per thread, MLP_p1=2),
//     256-bit ld/st, warp-shuffle halo, normal cache policy.

#define ROWS 256
#define LEN  131072
#define CH   (LEN / 8)     // 8-elem chunks per row = 16384
#define HROWS (ROWS / 2)   // 128

__device__ __forceinline__ float fused2(float x, float thresh, float pooled) {
    float e1 = __expf(10.0f * (thresh - x));
    float e2 = __expf(10.0f * (pooled - x));
    return __fdividef(x, (1.0f + e1) * (1.0f + e2));
}

__device__ __forceinline__ void ldg256(const float* p, float* r) {
    asm volatile("ld.global.v8.f32 {%0,%1,%2,%3,%4,%5,%6,%7}, [%8];"
                 : "=f"(r[0]), "=f"(r[1]), "=f"(r[2]), "=f"(r[3]),
                   "=f"(r[4]), "=f"(r[5]), "=f"(r[6]), "=f"(r[7])
                 : "l"(p));
}

__device__ __forceinline__ void stg256(float* p, const float* r) {
    asm volatile("st.global.v8.f32 [%0], {%1,%2,%3,%4,%5,%6,%7,%8};"
                 :: "l"(p),
                    "f"(r[0]), "f"(r[1]), "f"(r[2]), "f"(r[3]),
                    "f"(r[4]), "f"(r[5]), "f"(r[6]), "f"(r[7])
                 : "memory");
}

// sliding 5-max + fused sigmoids + stores for one 8-elem chunk
__device__ __forceinline__ void process8(const float e[8],
                                         float lx, float ly, float rx, float ry,
                                         float thresh,
                                         float* smooth_p, float* mask_p,
                                         int write_mask)
{
    float M01 = fmaxf(e[0], e[1]);
    float M23 = fmaxf(e[2], e[3]);
    float M45 = fmaxf(e[4], e[5]);
    float M67 = fmaxf(e[6], e[7]);
    float Mll = fmaxf(lx, ly);
    float Mrr = fmaxf(rx, ry);

    float p[8];
    p[0] = fmaxf(Mll,  fmaxf(M01, e[2]));
    p[1] = fmaxf(ly,   fmaxf(M01, M23));
    p[2] = fmaxf(M01,  fmaxf(M23, e[4]));
    p[3] = fmaxf(e[1], fmaxf(M23, M45));
    p[4] = fmaxf(e[2], fmaxf(M23, fmaxf(M45, e[6])));
    p[5] = fmaxf(e[3], fmaxf(M45, M67));
    p[6] = fmaxf(M45,  fmaxf(M67, rx));
    p[7] = fmaxf(e[5], fmaxf(M67, Mrr));

    float s[8];
#pragma unroll
    for (int i = 0; i < 8; i++)
        s[i] = fused2(e[i], thresh, p[i]);

    stg256(smooth_p, s);

    if (write_mask) {
        float m[8];
#pragma unroll
        for (int i = 0; i < 8; i++)
            m[i] = (s[i] >= thresh) ? 1.0f : 0.0f;
        stg256(mask_p, m);
    }
}

__global__ __launch_bounds__(256)
void peak_kernel(const float* __restrict__ in,
                 const float* __restrict__ logit_thresh,
                 float* __restrict__ out_smooth,
                 float* __restrict__ out_mask,
                 int write_mask)
{
    const int rowA = blockIdx.y;            // 0..127
    const int rowB = rowA + HROWS;          // 128..255
    const int t    = blockIdx.x * blockDim.x + threadIdx.x;  // chunk in row
    const unsigned lane = threadIdx.x & 31;

    const float* baseA = in + (size_t)rowA * LEN + 8 * (size_t)t;
    const float* baseB = in + (size_t)rowB * LEN + 8 * (size_t)t;

    // front-batched: two independent 256-bit loads
    float a[8], b[8];
    ldg256(baseA, a);
    ldg256(baseB, b);

    // halos via warp shuffle (both streams)
    float alx = __shfl_up_sync(0xFFFFFFFFu,   a[6], 1);
    float aly = __shfl_up_sync(0xFFFFFFFFu,   a[7], 1);
    float arx = __shfl_down_sync(0xFFFFFFFFu, a[0], 1);
    float ary = __shfl_down_sync(0xFFFFFFFFu, a[1], 1);
    float blx = __shfl_up_sync(0xFFFFFFFFu,   b[6], 1);
    float bly = __shfl_up_sync(0xFFFFFFFFu,   b[7], 1);
    float brx = __shfl_down_sync(0xFFFFFFFFu, b[0], 1);
    float bry = __shfl_down_sync(0xFFFFFFFFu, b[1], 1);

    if (lane == 0) {
        if (t > 0) {
            float2 pa = *reinterpret_cast<const float2*>(baseA - 2);
            float2 pb = *reinterpret_cast<const float2*>(baseB - 2);
            alx = pa.x; aly = pa.y;
            blx = pb.x; bly = pb.y;
        } else {
            alx = a[0]; aly = a[0];   // edge replicate
            blx = b[0]; bly = b[0];
        }
    }
    if (lane == 31) {
        if (t < CH - 1) {
            float2 na = *reinterpret_cast<const float2*>(baseA + 8);
            float2 nb = *reinterpret_cast<const float2*>(baseB + 8);
            arx = na.x; ary = na.y;
            brx = nb.x; bry = nb.y;
        } else {
            arx = a[7]; ary = a[7];   // edge replicate
            brx = b[7]; bry = b[7];
        }
    }

    float tl = logit_thresh[0];
    float thresh = __fdividef(1.0f, 1.0f + __expf(-tl));

    const size_t offA = (size_t)rowA * LEN + 8 * (size_t)t;
    const size_t offB = (size_t)rowB * LEN + 8 * (size_t)t;

    process8(a, alx, aly, arx, ary, thresh,
             out_smooth + offA, out_mask + offA, write_mask);
    process8(b, blx, bly, brx, bry, thresh,
             out_smooth + offB, out_mask + offB, write_mask);
}

extern "C" void kernel_launch(void* const* d_in, const int* in_sizes, int n_in,
                              void* d_out, int out_size)
{
    const float* peak_map     = (const float*)d_in[0];
    const float* logit_thresh = (const float*)d_in[1];
    float* out = (float*)d_out;

    const long long N = (long long)ROWS * LEN;   // 33,554,432
    int write_mask = (out_size >= 2 * N) ? 1 : 0;

    dim3 grid(CH / 256, HROWS);   // (64, 128)
    peak_kernel<<<grid, 256>>>(peak_map, logit_thresh,
                               out, out + N, write_mask);
}